// round 13
// baseline (speedup 1.0000x reference)
#include <cuda_runtime.h>
#include <cuda_fp16.h>
#include <cstdint>

#define EMB   768
#define HS    64
#define BATCH 4
#define SEQ   4096
#define KSPLIT 2
#define TOT   (BATCH * SEQ * HS)
#define NQT   (SEQ / 128)

// Projection outputs, fp16. Q pre-scaled by log2(e)/sqrt(768). Row-major.
__device__ __half g_Qh[TOT];
__device__ __half g_Kh[TOT];
__device__ __half g_Vh[TOT];
// Key-split partials: O fp16, l fp32.
__device__ __half g_Oph[KSPLIT * TOT];
__device__ float  g_lp[KSPLIT * BATCH * SEQ];
// Per (batch, q-tile) completion counters (reset to 0 by consumer -> replay-safe).
__device__ unsigned int g_cnt[BATCH * NQT];
// Pre-swizzled fp16 weight tile images: 24 K-blocks x (32 rows x 384B).
__device__ unsigned char g_Wimg[24 * 12288];

// ---------------------------------------------------------------------------
// helpers
// ---------------------------------------------------------------------------
__device__ __forceinline__ uint32_t smem_u32(const void* p) {
    uint32_t a;
    asm("{ .reg .u64 t; cvta.to.shared.u64 t, %1; cvt.u32.u64 %0, t; }"
        : "=r"(a) : "l"(p));
    return a;
}

#define LDSM_X4(r0, r1, r2, r3, addr) \
    asm volatile("ldmatrix.sync.aligned.m8n8.x4.shared.b16 {%0,%1,%2,%3}, [%4];" \
                 : "=r"(r0), "=r"(r1), "=r"(r2), "=r"(r3) : "r"(addr))

#define LDSM_X4T(r0, r1, r2, r3, addr) \
    asm volatile("ldmatrix.sync.aligned.m8n8.x4.trans.shared.b16 {%0,%1,%2,%3}, [%4];" \
                 : "=r"(r0), "=r"(r1), "=r"(r2), "=r"(r3) : "r"(addr))

__device__ __forceinline__ void mma16816(float* c, const uint32_t* a,
                                         uint32_t b0, uint32_t b1) {
    asm volatile(
        "mma.sync.aligned.m16n8k16.row.col.f32.f16.f16.f32 "
        "{%0,%1,%2,%3}, {%4,%5,%6,%7}, {%8,%9}, {%0,%1,%2,%3};"
        : "+f"(c[0]), "+f"(c[1]), "+f"(c[2]), "+f"(c[3])
        : "r"(a[0]), "r"(a[1]), "r"(a[2]), "r"(a[3]), "r"(b0), "r"(b1));
}

#define CP16(dst, src) \
    asm volatile("cp.async.cg.shared.global [%0], [%1], 16;" :: "r"(dst), "l"(src))
#define CP_COMMIT() asm volatile("cp.async.commit_group;")
#define CP_WAIT(n)  asm volatile("cp.async.wait_group %0;" :: "n"(n))

// fp16x2 exp2 (one MUFU op per two values)
#define EX2_H2(out, in) \
    asm("ex2.approx.f16x2 %0, %1;" : "=r"(out) : "r"(in))

// XOR-swizzled smem byte offset, 128B rows (8 x 16B chunks)
#define SW8(r, c)  ((uint32_t)((r) * 128 + ((((c) ^ ((r) & 7))) << 4)))
// W image swizzle: 384B rows = 24 chunks, XOR within each 8-chunk group
#define SWW(r, c)  ((uint32_t)((r) * 384 + ((((c) & ~7) | (((c) & 7) ^ ((r) & 7))) << 4)))

// Q scale = log2(e) / sqrt(768)
#define QSCALE 0.05205877870f
// all-ones fp16x2 B fragment
#define ONES_H2 0x3C003C00u

// ---------------------------------------------------------------------------
// One-time weight conversion (unchanged).
// ---------------------------------------------------------------------------
__global__ __launch_bounds__(256)
void wconv_kernel(const float* __restrict__ Wk,
                  const float* __restrict__ Wq,
                  const float* __restrict__ Wv)
{
    int idx = blockIdx.x * 256 + threadIdx.x;
    if (idx >= 24 * 32 * 24) return;
    int c  = idx % 24;
    int r  = (idx / 24) % 32;
    int bi = idx / (24 * 32);
    int k  = bi * 32 + r;
    int n  = c * 8;
    const float* src = (n < 64 ? Wq : (n < 128 ? Wk : Wv)) + (size_t)k * HS + (n & 63);
    float4 f0 = *(const float4*)(src);
    float4 f1 = *(const float4*)(src + 4);
    __half2 h0 = __floats2half2_rn(f0.x, f0.y);
    __half2 h1 = __floats2half2_rn(f0.z, f0.w);
    __half2 h2 = __floats2half2_rn(f1.x, f1.y);
    __half2 h3 = __floats2half2_rn(f1.z, f1.w);
    uint4 u;
    u.x = *(uint32_t*)&h0; u.y = *(uint32_t*)&h1;
    u.z = *(uint32_t*)&h2; u.w = *(uint32_t*)&h3;
    *(uint4*)(g_Wimg + (size_t)bi * 12288 + SWW(r, c)) = u;
}

// ---------------------------------------------------------------------------
// Fused projection GEMM, fp16 mma, cp.async double-buffered (round-11 proven).
// ---------------------------------------------------------------------------
#define XF0 0u
#define XF1 8192u
#define WB0 16384u
#define WB1 28672u
#define XHO 40960u
#define PROJ_SMEM_BYTES 49152

__global__ __launch_bounds__(256, 2)
void proj_kernel(const float* __restrict__ x)
{
    extern __shared__ __align__(1024) char smem[];
    const uint32_t sb = smem_u32(smem);
    const uint32_t XF[2] = {sb + XF0, sb + XF1};
    const uint32_t WB[2] = {sb + WB0, sb + WB1};
    const uint32_t XH    = sb + XHO;

    const int tid  = threadIdx.x;
    const int lane = tid & 31;
    const int warp = tid >> 5;
    const int g    = lane >> 2;
    const int t    = lane & 3;
    const int wm   = warp & 3;
    const int wn   = warp >> 2;
    const int row0 = blockIdx.x * 64;

    #pragma unroll
    for (int i = 0; i < 2; i++) {
        int ch = tid + i * 256;
        int r = ch >> 3, c = ch & 7;
        CP16(XF[0] + (uint32_t)(r * 128 + c * 16),
             x + (size_t)(row0 + r) * EMB + c * 4);
    }
    #pragma unroll
    for (int i = 0; i < 3; i++) {
        int ch = tid + i * 256;
        CP16(WB[0] + (uint32_t)(ch * 16), g_Wimg + (size_t)(ch * 16));
    }
    CP_COMMIT();

    float cacc[12][4];
    #pragma unroll
    for (int j = 0; j < 12; j++)
        #pragma unroll
        for (int k = 0; k < 4; k++) cacc[j][k] = 0.f;

    for (int it = 0; it < EMB / 32; it++) {
        const int cur = it & 1;
        if (it + 1 < EMB / 32) {
            const int nxt = (it + 1) & 1;
            const int k0n = (it + 1) * 32;
            #pragma unroll
            for (int i = 0; i < 2; i++) {
                int ch = tid + i * 256;
                int r = ch >> 3, c = ch & 7;
                CP16(XF[nxt] + (uint32_t)(r * 128 + c * 16),
                     x + (size_t)(row0 + r) * EMB + k0n + c * 4);
            }
            #pragma unroll
            for (int i = 0; i < 3; i++) {
                int ch = tid + i * 256;
                CP16(WB[nxt] + (uint32_t)(ch * 16),
                     g_Wimg + (size_t)(it + 1) * 12288 + ch * 16);
            }
            CP_COMMIT();
            CP_WAIT(1);
        } else {
            CP_WAIT(0);
        }
        __syncthreads();

        {
            int r = tid >> 2, q = tid & 3;
            float4 f0 = *(const float4*)(smem + (XF[cur] - sb) + r * 128 + q * 32);
            float4 f1 = *(const float4*)(smem + (XF[cur] - sb) + r * 128 + q * 32 + 16);
            __half2 h0 = __floats2half2_rn(f0.x, f0.y);
            __half2 h1 = __floats2half2_rn(f0.z, f0.w);
            __half2 h2 = __floats2half2_rn(f1.x, f1.y);
            __half2 h3 = __floats2half2_rn(f1.z, f1.w);
            uint4 u;
            u.x = *(uint32_t*)&h0; u.y = *(uint32_t*)&h1;
            u.z = *(uint32_t*)&h2; u.w = *(uint32_t*)&h3;
            *(uint4*)(smem + XHO + SW8(r, q)) = u;
        }
        __syncthreads();

        uint32_t af[2][4];
        #pragma unroll
        for (int s = 0; s < 2; s++) {
            int row = wm * 16 + (lane & 15);
            int ch  = 2 * s + (lane >> 4);
            LDSM_X4(af[s][0], af[s][1], af[s][2], af[s][3], XH + SW8(row, ch));
        }
        #pragma unroll
        for (int s = 0; s < 2; s++) {
            #pragma unroll
            for (int jj = 0; jj < 6; jj++) {
                int row = 16 * s + (lane & 15);
                int ch  = 2 * (wn * 6 + jj) + (lane >> 4);
                uint32_t b0, b1, b2, b3;
                LDSM_X4T(b0, b1, b2, b3, WB[cur] + SWW(row, ch));
                mma16816(cacc[2 * jj],     af[s], b0, b1);
                mma16816(cacc[2 * jj + 1], af[s], b2, b3);
            }
        }
        __syncthreads();
    }

    const int prow0 = row0 + wm * 16 + g;
    const int prow1 = prow0 + 8;
    #pragma unroll
    for (int j = 0; j < 12; j++) {
        int col = wn * 96 + 8 * j + 2 * t;
        __half* dst;
        float mul;
        int lc;
        if (col < 64)       { dst = g_Qh; mul = QSCALE; lc = col; }
        else if (col < 128) { dst = g_Kh; mul = 1.0f;   lc = col - 64; }
        else                { dst = g_Vh; mul = 1.0f;   lc = col - 128; }
        __half2 v0 = __floats2half2_rn(cacc[j][0] * mul, cacc[j][1] * mul);
        __half2 v1 = __floats2half2_rn(cacc[j][2] * mul, cacc[j][3] * mul);
        *(__half2*)(dst + (size_t)prow0 * HS + lc) = v0;
        *(__half2*)(dst + (size_t)prow1 * HS + lc) = v1;
    }
}

// ---------------------------------------------------------------------------
// fp16 flash attention — round-11 pipeline (best), fp16 partials, and the
// split-combine FUSED via a last-CTA-done counter (reduce kernel removed).
// ---------------------------------------------------------------------------
#define QOFS 0u
#define ATTN_SMEM_BYTES 81920
#define NIT (SEQ / 128 / KSPLIT)

__global__ __launch_bounds__(256, 2)
void attn_kernel(float* __restrict__ out)
{
    extern __shared__ __align__(1024) char smem[];
    __shared__ unsigned int s_old;
    const uint32_t sbase = smem_u32(smem);

    const int tid  = threadIdx.x;
    const int lane = tid & 31;
    const int warp = tid >> 5;
    const int g    = lane >> 2;
    const int t    = lane & 3;
    const int wb   = warp * 16;
    const int b    = blockIdx.y;
    const int ks   = blockIdx.z;
    const int q0   = blockIdx.x * 128;

    const uint32_t KB[2] = {16384u, 49152u};
    const uint32_t VB[2] = {32768u, 65536u};

    const __half* Qg = g_Qh + ((size_t)b * SEQ + q0) * HS;
    const __half* Kg = g_Kh + ((size_t)b * SEQ + (size_t)ks * (SEQ / KSPLIT)) * HS;
    const __half* Vg = g_Vh + ((size_t)b * SEQ + (size_t)ks * (SEQ / KSPLIT)) * HS;

    #pragma unroll
    for (int i = 0; i < 4; i++) {
        int gc = tid + i * 256;
        int r = gc >> 3, c = gc & 7;
        CP16(sbase + QOFS + SW8(r, c), Qg + (size_t)r * HS + c * 8);
        CP16(sbase + KB[0] + SW8(r, c), Kg + (size_t)r * HS + c * 8);
        CP16(sbase + VB[0] + SW8(r, c), Vg + (size_t)r * HS + c * 8);
    }
    CP_COMMIT();

    uint32_t qf[4][4];
    float lacc[4];
    #pragma unroll
    for (int k = 0; k < 4; k++) lacc[k] = 0.f;
    float oacc[8][4];
    #pragma unroll
    for (int j = 0; j < 8; j++)
        #pragma unroll
        for (int k = 0; k < 4; k++) oacc[j][k] = 0.f;

    const int prow0 = wb + g;
    const int prow1 = wb + g + 8;

    for (int it = 0; it < NIT; it++) {
        const int cur = it & 1;
        __syncthreads();

        if (it + 1 < NIT) {
            const int nxt = (it + 1) & 1;
            const int k0n = (it + 1) * 128;
            #pragma unroll
            for (int i = 0; i < 4; i++) {
                int gc = tid + i * 256;
                int r = gc >> 3, c = gc & 7;
                CP16(sbase + KB[nxt] + SW8(r, c),
                     Kg + (size_t)(k0n + r) * HS + c * 8);
                CP16(sbase + VB[nxt] + SW8(r, c),
                     Vg + (size_t)(k0n + r) * HS + c * 8);
            }
            CP_COMMIT();
            CP_WAIT(1);
        } else {
            CP_WAIT(0);
        }
        __syncthreads();

        if (it == 0) {
            #pragma unroll
            for (int s = 0; s < 4; s++) {
                int row = wb + (lane & 15);
                int ch  = 2 * s + (lane >> 4);
                LDSM_X4(qf[s][0], qf[s][1], qf[s][2], qf[s][3],
                        sbase + QOFS + SW8(row, ch));
            }
        }

        // ---- MMA1: S[16][128] = Q @ K^T ----
        float sacc[16][4];
        #pragma unroll
        for (int j = 0; j < 16; j++)
            #pragma unroll
            for (int k = 0; k < 4; k++) sacc[j][k] = 0.f;

        #pragma unroll
        for (int s = 0; s < 4; s++) {
            #pragma unroll
            for (int jj = 0; jj < 8; jj++) {
                int row = 8 * (2 * jj + (lane >> 4)) + (lane & 7);
                int ch  = 2 * s + ((lane >> 3) & 1);
                uint32_t b0, b1, b2, b3;
                LDSM_X4(b0, b1, b2, b3, sbase + KB[cur] + SW8(row, ch));
                mma16816(sacc[2 * jj],     qf[s], b0, b1);
                mma16816(sacc[2 * jj + 1], qf[s], b2, b3);
            }
        }

        // ---- per 16-key block: exp2(f16x2) -> P fragment, l via ones-MMA,
        //      then MMA2 ----
        #pragma unroll
        for (int s2 = 0; s2 < 8; s2++) {
            __half2 s01 = __floats2half2_rn(sacc[2 * s2][0],     sacc[2 * s2][1]);
            __half2 s23 = __floats2half2_rn(sacc[2 * s2][2],     sacc[2 * s2][3]);
            __half2 s45 = __floats2half2_rn(sacc[2 * s2 + 1][0], sacc[2 * s2 + 1][1]);
            __half2 s67 = __floats2half2_rn(sacc[2 * s2 + 1][2], sacc[2 * s2 + 1][3]);
            uint32_t pf[4];
            EX2_H2(pf[0], *(uint32_t*)&s01);
            EX2_H2(pf[1], *(uint32_t*)&s23);
            EX2_H2(pf[2], *(uint32_t*)&s45);
            EX2_H2(pf[3], *(uint32_t*)&s67);

            mma16816(lacc, pf, ONES_H2, ONES_H2);

            #pragma unroll
            for (int jj = 0; jj < 4; jj++) {
                int key = 16 * s2 + (lane & 15);
                int ch  = 2 * jj + (lane >> 4);
                uint32_t b0, b1, b2, b3;
                LDSM_X4T(b0, b1, b2, b3, sbase + VB[cur] + SW8(key, ch));
                mma16816(oacc[2 * jj],     pf, b0, b1);
                mma16816(oacc[2 * jj + 1], pf, b2, b3);
            }
        }
    }

    // ---- epilogue: publish partial, then last-CTA-done combine ----
    __half* Op = g_Oph + (size_t)ks * TOT + ((size_t)b * SEQ + q0) * HS;
    #pragma unroll
    for (int jh = 0; jh < 8; jh++) {
        int col = 8 * jh + 2 * t;
        __half2 v0 = __floats2half2_rn(oacc[jh][0], oacc[jh][1]);
        __half2 v1 = __floats2half2_rn(oacc[jh][2], oacc[jh][3]);
        *(__half2*)(Op + (size_t)prow0 * HS + col) = v0;
        *(__half2*)(Op + (size_t)prow1 * HS + col) = v1;
    }
    if (t == 0) {
        g_lp[(size_t)ks * BATCH * SEQ + (size_t)b * SEQ + q0 + prow0] = lacc[0];
        g_lp[(size_t)ks * BATCH * SEQ + (size_t)b * SEQ + q0 + prow1] = lacc[2];
    }

    __threadfence();
    if (tid == 0)
        s_old = atomicAdd(&g_cnt[b * NQT + blockIdx.x], 1);
    __syncthreads();
    if (s_old != 1) return;   // first finisher: partial published, done

    // second finisher: combine own registers with other split's partial
    __threadfence();          // acquire other's partial + l
    const int os = 1 - ks;
    const __half* Oo = g_Oph + (size_t)os * TOT + ((size_t)b * SEQ + q0) * HS;
    const float* lo  = g_lp + (size_t)os * BATCH * SEQ + (size_t)b * SEQ + q0;
    const float* lm  = g_lp + (size_t)ks * BATCH * SEQ + (size_t)b * SEQ + q0;

    float inv0 = 1.0f / (lm[prow0] + lo[prow0]);
    float inv1 = 1.0f / (lm[prow1] + lo[prow1]);

    float* O = out + ((size_t)b * SEQ + q0) * HS;
    #pragma unroll
    for (int jh = 0; jh < 8; jh++) {
        int col = 8 * jh + 2 * t;
        float2 a0 = __half22float2(*(const __half2*)(Oo + (size_t)prow0 * HS + col));
        float2 a1 = __half22float2(*(const __half2*)(Oo + (size_t)prow1 * HS + col));
        float2 v0 = make_float2((oacc[jh][0] + a0.x) * inv0,
                                (oacc[jh][1] + a0.y) * inv0);
        float2 v1 = make_float2((oacc[jh][2] + a1.x) * inv1,
                                (oacc[jh][3] + a1.y) * inv1);
        *(float2*)(O + (size_t)prow0 * HS + col) = v0;
        *(float2*)(O + (size_t)prow1 * HS + col) = v1;
    }

    if (tid == 0)
        g_cnt[b * NQT + blockIdx.x] = 0;   // reset for next replay
}

// ---------------------------------------------------------------------------
extern "C" void kernel_launch(void* const* d_in, const int* in_sizes, int n_in,
                              void* d_out, int out_size)
{
    const float* x  = (const float*)d_in[0];
    const float* Wk = (const float*)d_in[1];
    const float* Wq = (const float*)d_in[2];
    const float* Wv = (const float*)d_in[3];
    float* out = (float*)d_out;

    (void)in_sizes; (void)n_in; (void)out_size;

    cudaFuncSetAttribute(attn_kernel,
                         cudaFuncAttributeMaxDynamicSharedMemorySize,
                         ATTN_SMEM_BYTES);
    cudaFuncSetAttribute(proj_kernel,
                         cudaFuncAttributeMaxDynamicSharedMemorySize,
                         PROJ_SMEM_BYTES);

    wconv_kernel<<<(24 * 32 * 24 + 255) / 256, 256>>>(Wk, Wq, Wv);
    proj_kernel<<<BATCH * SEQ / 64, 256, PROJ_SMEM_BYTES>>>(x);

    dim3 agrid(SEQ / 128, BATCH, KSPLIT);
    attn_kernel<<<agrid, 256, ATTN_SMEM_BYTES>>>(out);
}

// round 14
// speedup vs baseline: 1.0278x; 1.0278x over previous
#include <cuda_runtime.h>
#include <cuda_fp16.h>
#include <cstdint>

#define EMB   768
#define HS    64
#define BATCH 4
#define SEQ   4096
#define KSPLIT 2
#define TOT   (BATCH * SEQ * HS)

// Projection outputs, fp16. Q pre-scaled by log2(e)/sqrt(768). Row-major.
__device__ __half g_Qh[TOT];
__device__ __half g_Kh[TOT];
__device__ __half g_Vh[TOT];
// Key-split partials: O fp16, l fp32.
__device__ __half g_Oph[KSPLIT * TOT];
__device__ float  g_lp[KSPLIT * BATCH * SEQ];
// Pre-swizzled fp16 weight tile images: 24 K-blocks x (32 rows x 384B).
__device__ unsigned char g_Wimg[24 * 12288];

// ---------------------------------------------------------------------------
// helpers
// ---------------------------------------------------------------------------
__device__ __forceinline__ uint32_t smem_u32(const void* p) {
    uint32_t a;
    asm("{ .reg .u64 t; cvta.to.shared.u64 t, %1; cvt.u32.u64 %0, t; }"
        : "=r"(a) : "l"(p));
    return a;
}

#define LDSM_X4(r0, r1, r2, r3, addr) \
    asm volatile("ldmatrix.sync.aligned.m8n8.x4.shared.b16 {%0,%1,%2,%3}, [%4];" \
                 : "=r"(r0), "=r"(r1), "=r"(r2), "=r"(r3) : "r"(addr))

#define LDSM_X4T(r0, r1, r2, r3, addr) \
    asm volatile("ldmatrix.sync.aligned.m8n8.x4.trans.shared.b16 {%0,%1,%2,%3}, [%4];" \
                 : "=r"(r0), "=r"(r1), "=r"(r2), "=r"(r3) : "r"(addr))

__device__ __forceinline__ void mma16816(float* c, const uint32_t* a,
                                         uint32_t b0, uint32_t b1) {
    asm volatile(
        "mma.sync.aligned.m16n8k16.row.col.f32.f16.f16.f32 "
        "{%0,%1,%2,%3}, {%4,%5,%6,%7}, {%8,%9}, {%0,%1,%2,%3};"
        : "+f"(c[0]), "+f"(c[1]), "+f"(c[2]), "+f"(c[3])
        : "r"(a[0]), "r"(a[1]), "r"(a[2]), "r"(a[3]), "r"(b0), "r"(b1));
}

#define CP16(dst, src) \
    asm volatile("cp.async.cg.shared.global [%0], [%1], 16;" :: "r"(dst), "l"(src))
#define CP_COMMIT() asm volatile("cp.async.commit_group;")
#define CP_WAIT(n)  asm volatile("cp.async.wait_group %0;" :: "n"(n))

// fp16x2 exp2 (one MUFU op per two values)
#define EX2_H2(out, in) \
    asm("ex2.approx.f16x2 %0, %1;" : "=r"(out) : "r"(in))

// XOR-swizzled smem byte offset, 128B rows (8 x 16B chunks)
#define SW8(r, c)  ((uint32_t)((r) * 128 + ((((c) ^ ((r) & 7))) << 4)))
// W image swizzle: 384B rows = 24 chunks, XOR within each 8-chunk group
#define SWW(r, c)  ((uint32_t)((r) * 384 + ((((c) & ~7) | (((c) & 7) ^ ((r) & 7))) << 4)))

// Q scale = log2(e) / sqrt(768)
#define QSCALE 0.05205877870f
// all-ones fp16x2 B fragment
#define ONES_H2 0x3C003C00u

// ---------------------------------------------------------------------------
// One-time weight conversion (unchanged).
// ---------------------------------------------------------------------------
__global__ __launch_bounds__(256)
void wconv_kernel(const float* __restrict__ Wk,
                  const float* __restrict__ Wq,
                  const float* __restrict__ Wv)
{
    int idx = blockIdx.x * 256 + threadIdx.x;
    if (idx >= 24 * 32 * 24) return;
    int c  = idx % 24;
    int r  = (idx / 24) % 32;
    int bi = idx / (24 * 32);
    int k  = bi * 32 + r;
    int n  = c * 8;
    const float* src = (n < 64 ? Wq : (n < 128 ? Wk : Wv)) + (size_t)k * HS + (n & 63);
    float4 f0 = *(const float4*)(src);
    float4 f1 = *(const float4*)(src + 4);
    __half2 h0 = __floats2half2_rn(f0.x, f0.y);
    __half2 h1 = __floats2half2_rn(f0.z, f0.w);
    __half2 h2 = __floats2half2_rn(f1.x, f1.y);
    __half2 h3 = __floats2half2_rn(f1.z, f1.w);
    uint4 u;
    u.x = *(uint32_t*)&h0; u.y = *(uint32_t*)&h1;
    u.z = *(uint32_t*)&h2; u.w = *(uint32_t*)&h3;
    *(uint4*)(g_Wimg + (size_t)bi * 12288 + SWW(r, c)) = u;
}

// ---------------------------------------------------------------------------
// Fused projection GEMM, fp16 mma, cp.async double-buffered (round-11 exact).
// ---------------------------------------------------------------------------
#define XF0 0u
#define XF1 8192u
#define WB0 16384u
#define WB1 28672u
#define XHO 40960u
#define PROJ_SMEM_BYTES 49152

__global__ __launch_bounds__(256, 2)
void proj_kernel(const float* __restrict__ x)
{
    extern __shared__ __align__(1024) char smem[];
    const uint32_t sb = smem_u32(smem);
    const uint32_t XF[2] = {sb + XF0, sb + XF1};
    const uint32_t WB[2] = {sb + WB0, sb + WB1};
    const uint32_t XH    = sb + XHO;

    const int tid  = threadIdx.x;
    const int lane = tid & 31;
    const int warp = tid >> 5;
    const int g    = lane >> 2;
    const int t    = lane & 3;
    const int wm   = warp & 3;
    const int wn   = warp >> 2;
    const int row0 = blockIdx.x * 64;

    #pragma unroll
    for (int i = 0; i < 2; i++) {
        int ch = tid + i * 256;
        int r = ch >> 3, c = ch & 7;
        CP16(XF[0] + (uint32_t)(r * 128 + c * 16),
             x + (size_t)(row0 + r) * EMB + c * 4);
    }
    #pragma unroll
    for (int i = 0; i < 3; i++) {
        int ch = tid + i * 256;
        CP16(WB[0] + (uint32_t)(ch * 16), g_Wimg + (size_t)(ch * 16));
    }
    CP_COMMIT();

    float cacc[12][4];
    #pragma unroll
    for (int j = 0; j < 12; j++)
        #pragma unroll
        for (int k = 0; k < 4; k++) cacc[j][k] = 0.f;

    for (int it = 0; it < EMB / 32; it++) {
        const int cur = it & 1;
        if (it + 1 < EMB / 32) {
            const int nxt = (it + 1) & 1;
            const int k0n = (it + 1) * 32;
            #pragma unroll
            for (int i = 0; i < 2; i++) {
                int ch = tid + i * 256;
                int r = ch >> 3, c = ch & 7;
                CP16(XF[nxt] + (uint32_t)(r * 128 + c * 16),
                     x + (size_t)(row0 + r) * EMB + k0n + c * 4);
            }
            #pragma unroll
            for (int i = 0; i < 3; i++) {
                int ch = tid + i * 256;
                CP16(WB[nxt] + (uint32_t)(ch * 16),
                     g_Wimg + (size_t)(it + 1) * 12288 + ch * 16);
            }
            CP_COMMIT();
            CP_WAIT(1);
        } else {
            CP_WAIT(0);
        }
        __syncthreads();

        {
            int r = tid >> 2, q = tid & 3;
            float4 f0 = *(const float4*)(smem + (XF[cur] - sb) + r * 128 + q * 32);
            float4 f1 = *(const float4*)(smem + (XF[cur] - sb) + r * 128 + q * 32 + 16);
            __half2 h0 = __floats2half2_rn(f0.x, f0.y);
            __half2 h1 = __floats2half2_rn(f0.z, f0.w);
            __half2 h2 = __floats2half2_rn(f1.x, f1.y);
            __half2 h3 = __floats2half2_rn(f1.z, f1.w);
            uint4 u;
            u.x = *(uint32_t*)&h0; u.y = *(uint32_t*)&h1;
            u.z = *(uint32_t*)&h2; u.w = *(uint32_t*)&h3;
            *(uint4*)(smem + XHO + SW8(r, q)) = u;
        }
        __syncthreads();

        uint32_t af[2][4];
        #pragma unroll
        for (int s = 0; s < 2; s++) {
            int row = wm * 16 + (lane & 15);
            int ch  = 2 * s + (lane >> 4);
            LDSM_X4(af[s][0], af[s][1], af[s][2], af[s][3], XH + SW8(row, ch));
        }
        #pragma unroll
        for (int s = 0; s < 2; s++) {
            #pragma unroll
            for (int jj = 0; jj < 6; jj++) {
                int row = 16 * s + (lane & 15);
                int ch  = 2 * (wn * 6 + jj) + (lane >> 4);
                uint32_t b0, b1, b2, b3;
                LDSM_X4T(b0, b1, b2, b3, WB[cur] + SWW(row, ch));
                mma16816(cacc[2 * jj],     af[s], b0, b1);
                mma16816(cacc[2 * jj + 1], af[s], b2, b3);
            }
        }
        __syncthreads();
    }

    const int prow0 = row0 + wm * 16 + g;
    const int prow1 = prow0 + 8;
    #pragma unroll
    for (int j = 0; j < 12; j++) {
        int col = wn * 96 + 8 * j + 2 * t;
        __half* dst;
        float mul;
        int lc;
        if (col < 64)       { dst = g_Qh; mul = QSCALE; lc = col; }
        else if (col < 128) { dst = g_Kh; mul = 1.0f;   lc = col - 64; }
        else                { dst = g_Vh; mul = 1.0f;   lc = col - 128; }
        __half2 v0 = __floats2half2_rn(cacc[j][0] * mul, cacc[j][1] * mul);
        __half2 v1 = __floats2half2_rn(cacc[j][2] * mul, cacc[j][3] * mul);
        *(__half2*)(dst + (size_t)prow0 * HS + lc) = v0;
        *(__half2*)(dst + (size_t)prow1 * HS + lc) = v1;
    }
}

// ---------------------------------------------------------------------------
// fp16 flash attention — round-11 pipeline EXACT (best measured), with fp16
// partial stores in the epilogue.
// SMEM: Q @0 (16K), K0 @16384, V0 @32768, K1 @49152, V1 @65536. Total 80K.
// ---------------------------------------------------------------------------
#define QOFS 0u
#define ATTN_SMEM_BYTES 81920
#define NIT (SEQ / 128 / KSPLIT)

__global__ __launch_bounds__(256, 2)
void attn_kernel()
{
    extern __shared__ __align__(1024) char smem[];
    const uint32_t sbase = smem_u32(smem);

    const int tid  = threadIdx.x;
    const int lane = tid & 31;
    const int warp = tid >> 5;
    const int g    = lane >> 2;
    const int t    = lane & 3;
    const int wb   = warp * 16;
    const int b    = blockIdx.y;
    const int ks   = blockIdx.z;
    const int q0   = blockIdx.x * 128;

    const uint32_t KB[2] = {16384u, 49152u};
    const uint32_t VB[2] = {32768u, 65536u};

    const __half* Qg = g_Qh + ((size_t)b * SEQ + q0) * HS;
    const __half* Kg = g_Kh + ((size_t)b * SEQ + (size_t)ks * (SEQ / KSPLIT)) * HS;
    const __half* Vg = g_Vh + ((size_t)b * SEQ + (size_t)ks * (SEQ / KSPLIT)) * HS;

    #pragma unroll
    for (int i = 0; i < 4; i++) {
        int gc = tid + i * 256;
        int r = gc >> 3, c = gc & 7;
        CP16(sbase + QOFS + SW8(r, c), Qg + (size_t)r * HS + c * 8);
        CP16(sbase + KB[0] + SW8(r, c), Kg + (size_t)r * HS + c * 8);
        CP16(sbase + VB[0] + SW8(r, c), Vg + (size_t)r * HS + c * 8);
    }
    CP_COMMIT();

    uint32_t qf[4][4];
    float lacc[4];
    #pragma unroll
    for (int k = 0; k < 4; k++) lacc[k] = 0.f;
    float oacc[8][4];
    #pragma unroll
    for (int j = 0; j < 8; j++)
        #pragma unroll
        for (int k = 0; k < 4; k++) oacc[j][k] = 0.f;

    const int prow0 = wb + g;
    const int prow1 = wb + g + 8;

    for (int it = 0; it < NIT; it++) {
        const int cur = it & 1;
        __syncthreads();

        if (it + 1 < NIT) {
            const int nxt = (it + 1) & 1;
            const int k0n = (it + 1) * 128;
            #pragma unroll
            for (int i = 0; i < 4; i++) {
                int gc = tid + i * 256;
                int r = gc >> 3, c = gc & 7;
                CP16(sbase + KB[nxt] + SW8(r, c),
                     Kg + (size_t)(k0n + r) * HS + c * 8);
                CP16(sbase + VB[nxt] + SW8(r, c),
                     Vg + (size_t)(k0n + r) * HS + c * 8);
            }
            CP_COMMIT();
            CP_WAIT(1);
        } else {
            CP_WAIT(0);
        }
        __syncthreads();

        if (it == 0) {
            #pragma unroll
            for (int s = 0; s < 4; s++) {
                int row = wb + (lane & 15);
                int ch  = 2 * s + (lane >> 4);
                LDSM_X4(qf[s][0], qf[s][1], qf[s][2], qf[s][3],
                        sbase + QOFS + SW8(row, ch));
            }
        }

        // ---- MMA1: S[16][128] = Q @ K^T ----
        float sacc[16][4];
        #pragma unroll
        for (int j = 0; j < 16; j++)
            #pragma unroll
            for (int k = 0; k < 4; k++) sacc[j][k] = 0.f;

        #pragma unroll
        for (int s = 0; s < 4; s++) {
            #pragma unroll
            for (int jj = 0; jj < 8; jj++) {
                int row = 8 * (2 * jj + (lane >> 4)) + (lane & 7);
                int ch  = 2 * s + ((lane >> 3) & 1);
                uint32_t b0, b1, b2, b3;
                LDSM_X4(b0, b1, b2, b3, sbase + KB[cur] + SW8(row, ch));
                mma16816(sacc[2 * jj],     qf[s], b0, b1);
                mma16816(sacc[2 * jj + 1], qf[s], b2, b3);
            }
        }

        // ---- per 16-key block: exp2(f16x2) -> P fragment, l via ones-MMA,
        //      then MMA2 ----
        #pragma unroll
        for (int s2 = 0; s2 < 8; s2++) {
            __half2 s01 = __floats2half2_rn(sacc[2 * s2][0],     sacc[2 * s2][1]);
            __half2 s23 = __floats2half2_rn(sacc[2 * s2][2],     sacc[2 * s2][3]);
            __half2 s45 = __floats2half2_rn(sacc[2 * s2 + 1][0], sacc[2 * s2 + 1][1]);
            __half2 s67 = __floats2half2_rn(sacc[2 * s2 + 1][2], sacc[2 * s2 + 1][3]);
            uint32_t pf[4];
            EX2_H2(pf[0], *(uint32_t*)&s01);
            EX2_H2(pf[1], *(uint32_t*)&s23);
            EX2_H2(pf[2], *(uint32_t*)&s45);
            EX2_H2(pf[3], *(uint32_t*)&s67);

            mma16816(lacc, pf, ONES_H2, ONES_H2);

            #pragma unroll
            for (int jj = 0; jj < 4; jj++) {
                int key = 16 * s2 + (lane & 15);
                int ch  = 2 * jj + (lane >> 4);
                uint32_t b0, b1, b2, b3;
                LDSM_X4T(b0, b1, b2, b3, sbase + VB[cur] + SW8(key, ch));
                mma16816(oacc[2 * jj],     pf, b0, b1);
                mma16816(oacc[2 * jj + 1], pf, b2, b3);
            }
        }
    }

    // ---- epilogue: fp16 partials ----
    __half* Op = g_Oph + (size_t)ks * TOT + ((size_t)b * SEQ + q0) * HS;
    #pragma unroll
    for (int jh = 0; jh < 8; jh++) {
        int col = 8 * jh + 2 * t;
        __half2 v0 = __floats2half2_rn(oacc[jh][0], oacc[jh][1]);
        __half2 v1 = __floats2half2_rn(oacc[jh][2], oacc[jh][3]);
        *(__half2*)(Op + (size_t)prow0 * HS + col) = v0;
        *(__half2*)(Op + (size_t)prow1 * HS + col) = v1;
    }
    if (t == 0) {
        g_lp[(size_t)ks * BATCH * SEQ + (size_t)b * SEQ + q0 + prow0] = lacc[0];
        g_lp[(size_t)ks * BATCH * SEQ + (size_t)b * SEQ + q0 + prow1] = lacc[2];
    }
}

// ---------------------------------------------------------------------------
// Combine split partials (fp16 in, fp32 out): out = (O0 + O1) / (l0 + l1).
// ---------------------------------------------------------------------------
__global__ __launch_bounds__(256)
void reduce_kernel(float* __restrict__ out)
{
    int gid = blockIdx.x * 256 + threadIdx.x;      // 0 .. TOT/8-1
    int row = gid >> 3;                            // 8 halves per thread, 64/row
    uint4 a = *(const uint4*)(g_Oph + 8 * (size_t)gid);
    uint4 c = *(const uint4*)(g_Oph + TOT + 8 * (size_t)gid);
    float inv = 1.0f / (g_lp[row] + g_lp[BATCH * SEQ + row]);

    float4 r0, r1;
    {
        float2 fa = __half22float2(*(__half2*)&a.x);
        float2 fc = __half22float2(*(__half2*)&c.x);
        r0.x = (fa.x + fc.x) * inv; r0.y = (fa.y + fc.y) * inv;
        fa = __half22float2(*(__half2*)&a.y);
        fc = __half22float2(*(__half2*)&c.y);
        r0.z = (fa.x + fc.x) * inv; r0.w = (fa.y + fc.y) * inv;
        fa = __half22float2(*(__half2*)&a.z);
        fc = __half22float2(*(__half2*)&c.z);
        r1.x = (fa.x + fc.x) * inv; r1.y = (fa.y + fc.y) * inv;
        fa = __half22float2(*(__half2*)&a.w);
        fc = __half22float2(*(__half2*)&c.w);
        r1.z = (fa.x + fc.x) * inv; r1.w = (fa.y + fc.y) * inv;
    }
    *(float4*)(out + 8 * (size_t)gid)     = r0;
    *(float4*)(out + 8 * (size_t)gid + 4) = r1;
}

// ---------------------------------------------------------------------------
extern "C" void kernel_launch(void* const* d_in, const int* in_sizes, int n_in,
                              void* d_out, int out_size)
{
    const float* x  = (const float*)d_in[0];
    const float* Wk = (const float*)d_in[1];
    const float* Wq = (const float*)d_in[2];
    const float* Wv = (const float*)d_in[3];
    float* out = (float*)d_out;

    (void)in_sizes; (void)n_in; (void)out_size;

    cudaFuncSetAttribute(attn_kernel,
                         cudaFuncAttributeMaxDynamicSharedMemorySize,
                         ATTN_SMEM_BYTES);
    cudaFuncSetAttribute(proj_kernel,
                         cudaFuncAttributeMaxDynamicSharedMemorySize,
                         PROJ_SMEM_BYTES);

    wconv_kernel<<<(24 * 32 * 24 + 255) / 256, 256>>>(Wk, Wq, Wv);
    proj_kernel<<<BATCH * SEQ / 64, 256, PROJ_SMEM_BYTES>>>(x);

    dim3 agrid(SEQ / 128, BATCH, KSPLIT);
    attn_kernel<<<agrid, 256, ATTN_SMEM_BYTES>>>();

    reduce_kernel<<<TOT / 8 / 256, 256>>>(out);
}

// round 15
// speedup vs baseline: 1.0290x; 1.0011x over previous
#include <cuda_runtime.h>
#include <cuda_fp16.h>
#include <cstdint>

#define EMB   768
#define HS    64
#define BATCH 4
#define SEQ   4096
#define KSPLIT 2
#define TOT   (BATCH * SEQ * HS)

// Projection outputs, fp16. Q pre-scaled by log2(e)/sqrt(768). Row-major.
__device__ __half g_Qh[TOT];
__device__ __half g_Kh[TOT];
__device__ __half g_Vh[TOT];
// Key-split partials: O fp32, l fp32 (round-11 best config).
__device__ float  g_Op[KSPLIT * TOT];
__device__ float  g_lp[KSPLIT * BATCH * SEQ];
// Pre-swizzled fp16 weight tile images: 24 K-blocks x (32 rows x 384B).
__device__ unsigned char g_Wimg[24 * 12288];

// ---------------------------------------------------------------------------
// helpers
// ---------------------------------------------------------------------------
__device__ __forceinline__ uint32_t smem_u32(const void* p) {
    uint32_t a;
    asm("{ .reg .u64 t; cvta.to.shared.u64 t, %1; cvt.u32.u64 %0, t; }"
        : "=r"(a) : "l"(p));
    return a;
}

#define LDSM_X4(r0, r1, r2, r3, addr) \
    asm volatile("ldmatrix.sync.aligned.m8n8.x4.shared.b16 {%0,%1,%2,%3}, [%4];" \
                 : "=r"(r0), "=r"(r1), "=r"(r2), "=r"(r3) : "r"(addr))

#define LDSM_X4T(r0, r1, r2, r3, addr) \
    asm volatile("ldmatrix.sync.aligned.m8n8.x4.trans.shared.b16 {%0,%1,%2,%3}, [%4];" \
                 : "=r"(r0), "=r"(r1), "=r"(r2), "=r"(r3) : "r"(addr))

__device__ __forceinline__ void mma16816(float* c, const uint32_t* a,
                                         uint32_t b0, uint32_t b1) {
    asm volatile(
        "mma.sync.aligned.m16n8k16.row.col.f32.f16.f16.f32 "
        "{%0,%1,%2,%3}, {%4,%5,%6,%7}, {%8,%9}, {%0,%1,%2,%3};"
        : "+f"(c[0]), "+f"(c[1]), "+f"(c[2]), "+f"(c[3])
        : "r"(a[0]), "r"(a[1]), "r"(a[2]), "r"(a[3]), "r"(b0), "r"(b1));
}

#define CP16(dst, src) \
    asm volatile("cp.async.cg.shared.global [%0], [%1], 16;" :: "r"(dst), "l"(src))
#define CP_COMMIT() asm volatile("cp.async.commit_group;")
#define CP_WAIT(n)  asm volatile("cp.async.wait_group %0;" :: "n"(n))

// fp16x2 exp2 (one MUFU op per two values)
#define EX2_H2(out, in) \
    asm("ex2.approx.f16x2 %0, %1;" : "=r"(out) : "r"(in))

// XOR-swizzled smem byte offset, 128B rows (8 x 16B chunks)
#define SW8(r, c)  ((uint32_t)((r) * 128 + ((((c) ^ ((r) & 7))) << 4)))
// W image swizzle: 384B rows = 24 chunks, XOR within each 8-chunk group
#define SWW(r, c)  ((uint32_t)((r) * 384 + ((((c) & ~7) | (((c) & 7) ^ ((r) & 7))) << 4)))

// Q scale = log2(e) / sqrt(768)
#define QSCALE 0.05205877870f
// all-ones fp16x2 B fragment
#define ONES_H2 0x3C003C00u

// ---------------------------------------------------------------------------
// One-time weight conversion, latency-optimized: one 8B half-chunk per thread
// (1 independent LDG.128 + 4 CVT + STG.64), 36864 threads, grid 144.
// ---------------------------------------------------------------------------
__global__ __launch_bounds__(256)
void wconv_kernel(const float* __restrict__ Wk,
                  const float* __restrict__ Wq,
                  const float* __restrict__ Wv)
{
    int idx = blockIdx.x * 256 + threadIdx.x;
    if (idx >= 24 * 32 * 24 * 2) return;
    int h  = idx & 1;                 // which 8B half of the 16B chunk
    int c  = (idx >> 1) % 24;
    int r  = ((idx >> 1) / 24) % 32;
    int bi = idx >> 1 >> 5 >> 3 == 0 ? (idx / (2 * 24 * 32)) : (idx / (2 * 24 * 32));
    bi = idx / (2 * 24 * 32);
    int k  = bi * 32 + r;
    int n  = c * 8 + h * 4;
    const float* src = (n < 64 ? Wq : (n < 128 ? Wk : Wv)) + (size_t)k * HS + (n & 63);
    float4 f = *(const float4*)(src);
    __half2 h0 = __floats2half2_rn(f.x, f.y);
    __half2 h1 = __floats2half2_rn(f.z, f.w);
    uint2 u;
    u.x = *(uint32_t*)&h0;
    u.y = *(uint32_t*)&h1;
    *(uint2*)(g_Wimg + (size_t)bi * 12288 + SWW(r, c) + h * 8) = u;
}

// ---------------------------------------------------------------------------
// Fused projection GEMM, fp16 mma, cp.async double-buffered (round-11 exact).
// ---------------------------------------------------------------------------
#define XF0 0u
#define XF1 8192u
#define WB0 16384u
#define WB1 28672u
#define XHO 40960u
#define PROJ_SMEM_BYTES 49152

__global__ __launch_bounds__(256, 2)
void proj_kernel(const float* __restrict__ x)
{
    extern __shared__ __align__(1024) char smem[];
    const uint32_t sb = smem_u32(smem);
    const uint32_t XF[2] = {sb + XF0, sb + XF1};
    const uint32_t WB[2] = {sb + WB0, sb + WB1};
    const uint32_t XH    = sb + XHO;

    const int tid  = threadIdx.x;
    const int lane = tid & 31;
    const int warp = tid >> 5;
    const int g    = lane >> 2;
    const int t    = lane & 3;
    const int wm   = warp & 3;
    const int wn   = warp >> 2;
    const int row0 = blockIdx.x * 64;

    #pragma unroll
    for (int i = 0; i < 2; i++) {
        int ch = tid + i * 256;
        int r = ch >> 3, c = ch & 7;
        CP16(XF[0] + (uint32_t)(r * 128 + c * 16),
             x + (size_t)(row0 + r) * EMB + c * 4);
    }
    #pragma unroll
    for (int i = 0; i < 3; i++) {
        int ch = tid + i * 256;
        CP16(WB[0] + (uint32_t)(ch * 16), g_Wimg + (size_t)(ch * 16));
    }
    CP_COMMIT();

    float cacc[12][4];
    #pragma unroll
    for (int j = 0; j < 12; j++)
        #pragma unroll
        for (int k = 0; k < 4; k++) cacc[j][k] = 0.f;

    for (int it = 0; it < EMB / 32; it++) {
        const int cur = it & 1;
        if (it + 1 < EMB / 32) {
            const int nxt = (it + 1) & 1;
            const int k0n = (it + 1) * 32;
            #pragma unroll
            for (int i = 0; i < 2; i++) {
                int ch = tid + i * 256;
                int r = ch >> 3, c = ch & 7;
                CP16(XF[nxt] + (uint32_t)(r * 128 + c * 16),
                     x + (size_t)(row0 + r) * EMB + k0n + c * 4);
            }
            #pragma unroll
            for (int i = 0; i < 3; i++) {
                int ch = tid + i * 256;
                CP16(WB[nxt] + (uint32_t)(ch * 16),
                     g_Wimg + (size_t)(it + 1) * 12288 + ch * 16);
            }
            CP_COMMIT();
            CP_WAIT(1);
        } else {
            CP_WAIT(0);
        }
        __syncthreads();

        {
            int r = tid >> 2, q = tid & 3;
            float4 f0 = *(const float4*)(smem + (XF[cur] - sb) + r * 128 + q * 32);
            float4 f1 = *(const float4*)(smem + (XF[cur] - sb) + r * 128 + q * 32 + 16);
            __half2 h0 = __floats2half2_rn(f0.x, f0.y);
            __half2 h1 = __floats2half2_rn(f0.z, f0.w);
            __half2 h2 = __floats2half2_rn(f1.x, f1.y);
            __half2 h3 = __floats2half2_rn(f1.z, f1.w);
            uint4 u;
            u.x = *(uint32_t*)&h0; u.y = *(uint32_t*)&h1;
            u.z = *(uint32_t*)&h2; u.w = *(uint32_t*)&h3;
            *(uint4*)(smem + XHO + SW8(r, q)) = u;
        }
        __syncthreads();

        uint32_t af[2][4];
        #pragma unroll
        for (int s = 0; s < 2; s++) {
            int row = wm * 16 + (lane & 15);
            int ch  = 2 * s + (lane >> 4);
            LDSM_X4(af[s][0], af[s][1], af[s][2], af[s][3], XH + SW8(row, ch));
        }
        #pragma unroll
        for (int s = 0; s < 2; s++) {
            #pragma unroll
            for (int jj = 0; jj < 6; jj++) {
                int row = 16 * s + (lane & 15);
                int ch  = 2 * (wn * 6 + jj) + (lane >> 4);
                uint32_t b0, b1, b2, b3;
                LDSM_X4T(b0, b1, b2, b3, WB[cur] + SWW(row, ch));
                mma16816(cacc[2 * jj],     af[s], b0, b1);
                mma16816(cacc[2 * jj + 1], af[s], b2, b3);
            }
        }
        __syncthreads();
    }

    const int prow0 = row0 + wm * 16 + g;
    const int prow1 = prow0 + 8;
    #pragma unroll
    for (int j = 0; j < 12; j++) {
        int col = wn * 96 + 8 * j + 2 * t;
        __half* dst;
        float mul;
        int lc;
        if (col < 64)       { dst = g_Qh; mul = QSCALE; lc = col; }
        else if (col < 128) { dst = g_Kh; mul = 1.0f;   lc = col - 64; }
        else                { dst = g_Vh; mul = 1.0f;   lc = col - 128; }
        __half2 v0 = __floats2half2_rn(cacc[j][0] * mul, cacc[j][1] * mul);
        __half2 v1 = __floats2half2_rn(cacc[j][2] * mul, cacc[j][3] * mul);
        *(__half2*)(dst + (size_t)prow0 * HS + lc) = v0;
        *(__half2*)(dst + (size_t)prow1 * HS + lc) = v1;
    }
}

// ---------------------------------------------------------------------------
// fp16 flash attention — round-11 EXACT (best measured): fp32 partials,
// double-buffered cp.async K/V, fp16x2 exp, l via ones-MMA.
// SMEM: Q @0 (16K), K0 @16384, V0 @32768, K1 @49152, V1 @65536. Total 80K.
// ---------------------------------------------------------------------------
#define QOFS 0u
#define ATTN_SMEM_BYTES 81920
#define NIT (SEQ / 128 / KSPLIT)

__global__ __launch_bounds__(256, 2)
void attn_kernel()
{
    extern __shared__ __align__(1024) char smem[];
    const uint32_t sbase = smem_u32(smem);

    const int tid  = threadIdx.x;
    const int lane = tid & 31;
    const int warp = tid >> 5;
    const int g    = lane >> 2;
    const int t    = lane & 3;
    const int wb   = warp * 16;
    const int b    = blockIdx.y;
    const int ks   = blockIdx.z;
    const int q0   = blockIdx.x * 128;

    const uint32_t KB[2] = {16384u, 49152u};
    const uint32_t VB[2] = {32768u, 65536u};

    const __half* Qg = g_Qh + ((size_t)b * SEQ + q0) * HS;
    const __half* Kg = g_Kh + ((size_t)b * SEQ + (size_t)ks * (SEQ / KSPLIT)) * HS;
    const __half* Vg = g_Vh + ((size_t)b * SEQ + (size_t)ks * (SEQ / KSPLIT)) * HS;

    #pragma unroll
    for (int i = 0; i < 4; i++) {
        int gc = tid + i * 256;
        int r = gc >> 3, c = gc & 7;
        CP16(sbase + QOFS + SW8(r, c), Qg + (size_t)r * HS + c * 8);
        CP16(sbase + KB[0] + SW8(r, c), Kg + (size_t)r * HS + c * 8);
        CP16(sbase + VB[0] + SW8(r, c), Vg + (size_t)r * HS + c * 8);
    }
    CP_COMMIT();

    uint32_t qf[4][4];
    float lacc[4];
    #pragma unroll
    for (int k = 0; k < 4; k++) lacc[k] = 0.f;
    float oacc[8][4];
    #pragma unroll
    for (int j = 0; j < 8; j++)
        #pragma unroll
        for (int k = 0; k < 4; k++) oacc[j][k] = 0.f;

    const int prow0 = wb + g;
    const int prow1 = wb + g + 8;

    for (int it = 0; it < NIT; it++) {
        const int cur = it & 1;
        __syncthreads();

        if (it + 1 < NIT) {
            const int nxt = (it + 1) & 1;
            const int k0n = (it + 1) * 128;
            #pragma unroll
            for (int i = 0; i < 4; i++) {
                int gc = tid + i * 256;
                int r = gc >> 3, c = gc & 7;
                CP16(sbase + KB[nxt] + SW8(r, c),
                     Kg + (size_t)(k0n + r) * HS + c * 8);
                CP16(sbase + VB[nxt] + SW8(r, c),
                     Vg + (size_t)(k0n + r) * HS + c * 8);
            }
            CP_COMMIT();
            CP_WAIT(1);
        } else {
            CP_WAIT(0);
        }
        __syncthreads();

        if (it == 0) {
            #pragma unroll
            for (int s = 0; s < 4; s++) {
                int row = wb + (lane & 15);
                int ch  = 2 * s + (lane >> 4);
                LDSM_X4(qf[s][0], qf[s][1], qf[s][2], qf[s][3],
                        sbase + QOFS + SW8(row, ch));
            }
        }

        // ---- MMA1: S[16][128] = Q @ K^T ----
        float sacc[16][4];
        #pragma unroll
        for (int j = 0; j < 16; j++)
            #pragma unroll
            for (int k = 0; k < 4; k++) sacc[j][k] = 0.f;

        #pragma unroll
        for (int s = 0; s < 4; s++) {
            #pragma unroll
            for (int jj = 0; jj < 8; jj++) {
                int row = 8 * (2 * jj + (lane >> 4)) + (lane & 7);
                int ch  = 2 * s + ((lane >> 3) & 1);
                uint32_t b0, b1, b2, b3;
                LDSM_X4(b0, b1, b2, b3, sbase + KB[cur] + SW8(row, ch));
                mma16816(sacc[2 * jj],     qf[s], b0, b1);
                mma16816(sacc[2 * jj + 1], qf[s], b2, b3);
            }
        }

        // ---- per 16-key block: exp2(f16x2) -> P fragment, l via ones-MMA,
        //      then MMA2 ----
        #pragma unroll
        for (int s2 = 0; s2 < 8; s2++) {
            __half2 s01 = __floats2half2_rn(sacc[2 * s2][0],     sacc[2 * s2][1]);
            __half2 s23 = __floats2half2_rn(sacc[2 * s2][2],     sacc[2 * s2][3]);
            __half2 s45 = __floats2half2_rn(sacc[2 * s2 + 1][0], sacc[2 * s2 + 1][1]);
            __half2 s67 = __floats2half2_rn(sacc[2 * s2 + 1][2], sacc[2 * s2 + 1][3]);
            uint32_t pf[4];
            EX2_H2(pf[0], *(uint32_t*)&s01);
            EX2_H2(pf[1], *(uint32_t*)&s23);
            EX2_H2(pf[2], *(uint32_t*)&s45);
            EX2_H2(pf[3], *(uint32_t*)&s67);

            mma16816(lacc, pf, ONES_H2, ONES_H2);

            #pragma unroll
            for (int jj = 0; jj < 4; jj++) {
                int key = 16 * s2 + (lane & 15);
                int ch  = 2 * jj + (lane >> 4);
                uint32_t b0, b1, b2, b3;
                LDSM_X4T(b0, b1, b2, b3, sbase + VB[cur] + SW8(key, ch));
                mma16816(oacc[2 * jj],     pf, b0, b1);
                mma16816(oacc[2 * jj + 1], pf, b2, b3);
            }
        }
    }

    // ---- epilogue: fp32 partials (round-11 best) ----
    float* Op = g_Op + (size_t)ks * TOT + ((size_t)b * SEQ + q0) * HS;
    #pragma unroll
    for (int jh = 0; jh < 8; jh++) {
        int col = 8 * jh + 2 * t;
        *(float2*)(Op + (size_t)prow0 * HS + col) = make_float2(oacc[jh][0], oacc[jh][1]);
        *(float2*)(Op + (size_t)prow1 * HS + col) = make_float2(oacc[jh][2], oacc[jh][3]);
    }
    if (t == 0) {
        g_lp[(size_t)ks * BATCH * SEQ + (size_t)b * SEQ + q0 + prow0] = lacc[0];
        g_lp[(size_t)ks * BATCH * SEQ + (size_t)b * SEQ + q0 + prow1] = lacc[2];
    }
}

// ---------------------------------------------------------------------------
// Combine split partials: out = (O0 + O1) / (l0 + l1). Round-11 exact.
// ---------------------------------------------------------------------------
__global__ __launch_bounds__(256)
void reduce_kernel(float* __restrict__ out)
{
    int gid = blockIdx.x * 256 + threadIdx.x;       // 0 .. TOT/4-1
    int row = gid >> 4;
    float4 a = *(const float4*)(g_Op + 4 * (size_t)gid);
    float4 c = *(const float4*)(g_Op + TOT + 4 * (size_t)gid);
    float inv = 1.0f / (g_lp[row] + g_lp[BATCH * SEQ + row]);
    float4 r;
    r.x = (a.x + c.x) * inv;
    r.y = (a.y + c.y) * inv;
    r.z = (a.z + c.z) * inv;
    r.w = (a.w + c.w) * inv;
    *(float4*)(out + 4 * (size_t)gid) = r;
}

// ---------------------------------------------------------------------------
extern "C" void kernel_launch(void* const* d_in, const int* in_sizes, int n_in,
                              void* d_out, int out_size)
{
    const float* x  = (const float*)d_in[0];
    const float* Wk = (const float*)d_in[1];
    const float* Wq = (const float*)d_in[2];
    const float* Wv = (const float*)d_in[3];
    float* out = (float*)d_out;

    (void)in_sizes; (void)n_in; (void)out_size;

    cudaFuncSetAttribute(attn_kernel,
                         cudaFuncAttributeMaxDynamicSharedMemorySize,
                         ATTN_SMEM_BYTES);
    cudaFuncSetAttribute(proj_kernel,
                         cudaFuncAttributeMaxDynamicSharedMemorySize,
                         PROJ_SMEM_BYTES);

    wconv_kernel<<<(24 * 32 * 24 * 2 + 255) / 256, 256>>>(Wk, Wq, Wv);
    proj_kernel<<<BATCH * SEQ / 64, 256, PROJ_SMEM_BYTES>>>(x);

    dim3 agrid(SEQ / 128, BATCH, KSPLIT);
    attn_kernel<<<agrid, 256, ATTN_SMEM_BYTES>>>();

    reduce_kernel<<<TOT / 4 / 256, 256>>>(out);
}

// round 16
// speedup vs baseline: 1.0489x; 1.0194x over previous
#include <cuda_runtime.h>
#include <cuda_fp16.h>
#include <cstdint>

#define EMB   768
#define HS    64
#define BATCH 4
#define SEQ   4096
#define KSPLIT 2
#define TOT   (BATCH * SEQ * HS)

// Projection outputs, fp16. Q pre-scaled by log2(e)/sqrt(768). Row-major.
__device__ __half g_Qh[TOT];
__device__ __half g_Kh[TOT];
__device__ __half g_Vh[TOT];
// Key-split partials: O fp32, l fp32.
__device__ float  g_Op[KSPLIT * TOT];
__device__ float  g_lp[KSPLIT * BATCH * SEQ];
// Pre-swizzled fp16 weight tile images: 24 K-blocks x (32 rows x 384B).
__device__ unsigned char g_Wimg[24 * 12288];

// ---------------------------------------------------------------------------
// helpers
// ---------------------------------------------------------------------------
__device__ __forceinline__ uint32_t smem_u32(const void* p) {
    uint32_t a;
    asm("{ .reg .u64 t; cvta.to.shared.u64 t, %1; cvt.u32.u64 %0, t; }"
        : "=r"(a) : "l"(p));
    return a;
}

#define LDSM_X4(r0, r1, r2, r3, addr) \
    asm volatile("ldmatrix.sync.aligned.m8n8.x4.shared.b16 {%0,%1,%2,%3}, [%4];" \
                 : "=r"(r0), "=r"(r1), "=r"(r2), "=r"(r3) : "r"(addr))

#define LDSM_X4T(r0, r1, r2, r3, addr) \
    asm volatile("ldmatrix.sync.aligned.m8n8.x4.trans.shared.b16 {%0,%1,%2,%3}, [%4];" \
                 : "=r"(r0), "=r"(r1), "=r"(r2), "=r"(r3) : "r"(addr))

__device__ __forceinline__ void mma16816(float* c, const uint32_t* a,
                                         uint32_t b0, uint32_t b1) {
    asm volatile(
        "mma.sync.aligned.m16n8k16.row.col.f32.f16.f16.f32 "
        "{%0,%1,%2,%3}, {%4,%5,%6,%7}, {%8,%9}, {%0,%1,%2,%3};"
        : "+f"(c[0]), "+f"(c[1]), "+f"(c[2]), "+f"(c[3])
        : "r"(a[0]), "r"(a[1]), "r"(a[2]), "r"(a[3]), "r"(b0), "r"(b1));
}

#define CP16(dst, src) \
    asm volatile("cp.async.cg.shared.global [%0], [%1], 16;" :: "r"(dst), "l"(src))
#define CP_COMMIT() asm volatile("cp.async.commit_group;")
#define CP_WAIT(n)  asm volatile("cp.async.wait_group %0;" :: "n"(n))

// fp16x2 exp2 (one MUFU op per two values)
#define EX2_H2(out, in) \
    asm("ex2.approx.f16x2 %0, %1;" : "=r"(out) : "r"(in))

// XOR-swizzled smem byte offset, 128B rows (8 x 16B chunks)
#define SW8(r, c)  ((uint32_t)((r) * 128 + ((((c) ^ ((r) & 7))) << 4)))
// W image swizzle: 384B rows = 24 chunks, XOR within each 8-chunk group
#define SWW(r, c)  ((uint32_t)((r) * 384 + ((((c) & ~7) | (((c) & 7) ^ ((r) & 7))) << 4)))

// Q scale = log2(e) / sqrt(768)
#define QSCALE 0.05205877870f
// all-ones fp16x2 B fragment
#define ONES_H2 0x3C003C00u

// ---------------------------------------------------------------------------
// One-time weight conversion (round-11 form).
// ---------------------------------------------------------------------------
__global__ __launch_bounds__(256)
void wconv_kernel(const float* __restrict__ Wk,
                  const float* __restrict__ Wq,
                  const float* __restrict__ Wv)
{
    int idx = blockIdx.x * 256 + threadIdx.x;
    if (idx >= 24 * 32 * 24) return;
    int c  = idx % 24;
    int r  = (idx / 24) % 32;
    int bi = idx / (24 * 32);
    int k  = bi * 32 + r;
    int n  = c * 8;
    const float* src = (n < 64 ? Wq : (n < 128 ? Wk : Wv)) + (size_t)k * HS + (n & 63);
    float4 f0 = *(const float4*)(src);
    float4 f1 = *(const float4*)(src + 4);
    __half2 h0 = __floats2half2_rn(f0.x, f0.y);
    __half2 h1 = __floats2half2_rn(f0.z, f0.w);
    __half2 h2 = __floats2half2_rn(f1.x, f1.y);
    __half2 h3 = __floats2half2_rn(f1.z, f1.w);
    uint4 u;
    u.x = *(uint32_t*)&h0; u.y = *(uint32_t*)&h1;
    u.z = *(uint32_t*)&h2; u.w = *(uint32_t*)&h3;
    *(uint4*)(g_Wimg + (size_t)bi * 12288 + SWW(r, c)) = u;
}

// ---------------------------------------------------------------------------
// Fused projection GEMM, fp16 mma, cp.async double-buffered (round-11 exact).
// ---------------------------------------------------------------------------
#define XF0 0u
#define XF1 8192u
#define WB0 16384u
#define WB1 28672u
#define XHO 40960u
#define PROJ_SMEM_BYTES 49152

__global__ __launch_bounds__(256, 2)
void proj_kernel(const float* __restrict__ x)
{
    extern __shared__ __align__(1024) char smem[];
    const uint32_t sb = smem_u32(smem);
    const uint32_t XF[2] = {sb + XF0, sb + XF1};
    const uint32_t WB[2] = {sb + WB0, sb + WB1};
    const uint32_t XH    = sb + XHO;

    const int tid  = threadIdx.x;
    const int lane = tid & 31;
    const int warp = tid >> 5;
    const int g    = lane >> 2;
    const int t    = lane & 3;
    const int wm   = warp & 3;
    const int wn   = warp >> 2;
    const int row0 = blockIdx.x * 64;

    #pragma unroll
    for (int i = 0; i < 2; i++) {
        int ch = tid + i * 256;
        int r = ch >> 3, c = ch & 7;
        CP16(XF[0] + (uint32_t)(r * 128 + c * 16),
             x + (size_t)(row0 + r) * EMB + c * 4);
    }
    #pragma unroll
    for (int i = 0; i < 3; i++) {
        int ch = tid + i * 256;
        CP16(WB[0] + (uint32_t)(ch * 16), g_Wimg + (size_t)(ch * 16));
    }
    CP_COMMIT();

    float cacc[12][4];
    #pragma unroll
    for (int j = 0; j < 12; j++)
        #pragma unroll
        for (int k = 0; k < 4; k++) cacc[j][k] = 0.f;

    for (int it = 0; it < EMB / 32; it++) {
        const int cur = it & 1;
        if (it + 1 < EMB / 32) {
            const int nxt = (it + 1) & 1;
            const int k0n = (it + 1) * 32;
            #pragma unroll
            for (int i = 0; i < 2; i++) {
                int ch = tid + i * 256;
                int r = ch >> 3, c = ch & 7;
                CP16(XF[nxt] + (uint32_t)(r * 128 + c * 16),
                     x + (size_t)(row0 + r) * EMB + k0n + c * 4);
            }
            #pragma unroll
            for (int i = 0; i < 3; i++) {
                int ch = tid + i * 256;
                CP16(WB[nxt] + (uint32_t)(ch * 16),
                     g_Wimg + (size_t)(it + 1) * 12288 + ch * 16);
            }
            CP_COMMIT();
            CP_WAIT(1);
        } else {
            CP_WAIT(0);
        }
        __syncthreads();

        {
            int r = tid >> 2, q = tid & 3;
            float4 f0 = *(const float4*)(smem + (XF[cur] - sb) + r * 128 + q * 32);
            float4 f1 = *(const float4*)(smem + (XF[cur] - sb) + r * 128 + q * 32 + 16);
            __half2 h0 = __floats2half2_rn(f0.x, f0.y);
            __half2 h1 = __floats2half2_rn(f0.z, f0.w);
            __half2 h2 = __floats2half2_rn(f1.x, f1.y);
            __half2 h3 = __floats2half2_rn(f1.z, f1.w);
            uint4 u;
            u.x = *(uint32_t*)&h0; u.y = *(uint32_t*)&h1;
            u.z = *(uint32_t*)&h2; u.w = *(uint32_t*)&h3;
            *(uint4*)(smem + XHO + SW8(r, q)) = u;
        }
        __syncthreads();

        uint32_t af[2][4];
        #pragma unroll
        for (int s = 0; s < 2; s++) {
            int row = wm * 16 + (lane & 15);
            int ch  = 2 * s + (lane >> 4);
            LDSM_X4(af[s][0], af[s][1], af[s][2], af[s][3], XH + SW8(row, ch));
        }
        #pragma unroll
        for (int s = 0; s < 2; s++) {
            #pragma unroll
            for (int jj = 0; jj < 6; jj++) {
                int row = 16 * s + (lane & 15);
                int ch  = 2 * (wn * 6 + jj) + (lane >> 4);
                uint32_t b0, b1, b2, b3;
                LDSM_X4T(b0, b1, b2, b3, WB[cur] + SWW(row, ch));
                mma16816(cacc[2 * jj],     af[s], b0, b1);
                mma16816(cacc[2 * jj + 1], af[s], b2, b3);
            }
        }
        __syncthreads();
    }

    const int prow0 = row0 + wm * 16 + g;
    const int prow1 = prow0 + 8;
    #pragma unroll
    for (int j = 0; j < 12; j++) {
        int col = wn * 96 + 8 * j + 2 * t;
        __half* dst;
        float mul;
        int lc;
        if (col < 64)       { dst = g_Qh; mul = QSCALE; lc = col; }
        else if (col < 128) { dst = g_Kh; mul = 1.0f;   lc = col - 64; }
        else                { dst = g_Vh; mul = 1.0f;   lc = col - 128; }
        __half2 v0 = __floats2half2_rn(cacc[j][0] * mul, cacc[j][1] * mul);
        __half2 v1 = __floats2half2_rn(cacc[j][2] * mul, cacc[j][3] * mul);
        *(__half2*)(dst + (size_t)prow0 * HS + lc) = v0;
        *(__half2*)(dst + (size_t)prow1 * HS + lc) = v1;
    }
}

// ---------------------------------------------------------------------------
// fp16 flash attention, BQ=256 (two 128-query halves share each K/V tile),
// single wave: grid (16, 4, 2) = 128 CTAs. Round-11 inner math per half.
// SMEM: Q @0 (32K), K0 @32768, V0 @49152, K1 @65536, V1 @81920. Total 96K.
// ---------------------------------------------------------------------------
#define QOFS 0u
#define ATTN_SMEM_BYTES 98304
#define NIT (SEQ / 128 / KSPLIT)

__global__ __launch_bounds__(256)
void attn_kernel()
{
    extern __shared__ __align__(1024) char smem[];
    const uint32_t sbase = smem_u32(smem);

    const int tid  = threadIdx.x;
    const int lane = tid & 31;
    const int warp = tid >> 5;
    const int g    = lane >> 2;
    const int t    = lane & 3;
    const int wb   = warp * 16;
    const int b    = blockIdx.y;
    const int ks   = blockIdx.z;
    const int q0   = blockIdx.x * 256;

    const uint32_t KB[2] = {32768u, 65536u};
    const uint32_t VB[2] = {49152u, 81920u};

    const __half* Qg = g_Qh + ((size_t)b * SEQ + q0) * HS;
    const __half* Kg = g_Kh + ((size_t)b * SEQ + (size_t)ks * (SEQ / KSPLIT)) * HS;
    const __half* Vg = g_Vh + ((size_t)b * SEQ + (size_t)ks * (SEQ / KSPLIT)) * HS;

    // ---- prologue: Q (256x64: 2048 chunks, 8/thread) + K/V tile 0 ----
    #pragma unroll
    for (int i = 0; i < 8; i++) {
        int gc = tid + i * 256;
        int r = gc >> 3, c = gc & 7;
        CP16(sbase + QOFS + SW8(r, c), Qg + (size_t)r * HS + c * 8);
    }
    #pragma unroll
    for (int i = 0; i < 4; i++) {
        int gc = tid + i * 256;
        int r = gc >> 3, c = gc & 7;
        CP16(sbase + KB[0] + SW8(r, c), Kg + (size_t)r * HS + c * 8);
        CP16(sbase + VB[0] + SW8(r, c), Vg + (size_t)r * HS + c * 8);
    }
    CP_COMMIT();

    uint32_t qf[2][4][4];
    float lacc[2][4];
    float oacc[2][8][4];
    #pragma unroll
    for (int h = 0; h < 2; h++) {
        #pragma unroll
        for (int k = 0; k < 4; k++) lacc[h][k] = 0.f;
        #pragma unroll
        for (int j = 0; j < 8; j++)
            #pragma unroll
            for (int k = 0; k < 4; k++) oacc[h][j][k] = 0.f;
    }

    const int prow0 = wb + g;
    const int prow1 = wb + g + 8;

    for (int it = 0; it < NIT; it++) {
        const int cur = it & 1;
        __syncthreads();

        if (it + 1 < NIT) {
            const int nxt = (it + 1) & 1;
            const int k0n = (it + 1) * 128;
            #pragma unroll
            for (int i = 0; i < 4; i++) {
                int gc = tid + i * 256;
                int r = gc >> 3, c = gc & 7;
                CP16(sbase + KB[nxt] + SW8(r, c),
                     Kg + (size_t)(k0n + r) * HS + c * 8);
                CP16(sbase + VB[nxt] + SW8(r, c),
                     Vg + (size_t)(k0n + r) * HS + c * 8);
            }
            CP_COMMIT();
            CP_WAIT(1);
        } else {
            CP_WAIT(0);
        }
        __syncthreads();

        if (it == 0) {
            #pragma unroll
            for (int h = 0; h < 2; h++)
                #pragma unroll
                for (int s = 0; s < 4; s++) {
                    int row = h * 128 + wb + (lane & 15);
                    int ch  = 2 * s + (lane >> 4);
                    LDSM_X4(qf[h][s][0], qf[h][s][1], qf[h][s][2], qf[h][s][3],
                            sbase + QOFS + SW8(row, ch));
                }
        }

        // ---- two query halves share this K/V tile ----
        #pragma unroll
        for (int h = 0; h < 2; h++) {
            // MMA1: S[16][128] = Q_h @ K^T
            float sacc[16][4];
            #pragma unroll
            for (int j = 0; j < 16; j++)
                #pragma unroll
                for (int k = 0; k < 4; k++) sacc[j][k] = 0.f;

            #pragma unroll
            for (int s = 0; s < 4; s++) {
                #pragma unroll
                for (int jj = 0; jj < 8; jj++) {
                    int row = 8 * (2 * jj + (lane >> 4)) + (lane & 7);
                    int ch  = 2 * s + ((lane >> 3) & 1);
                    uint32_t b0, b1, b2, b3;
                    LDSM_X4(b0, b1, b2, b3, sbase + KB[cur] + SW8(row, ch));
                    mma16816(sacc[2 * jj],     qf[h][s], b0, b1);
                    mma16816(sacc[2 * jj + 1], qf[h][s], b2, b3);
                }
            }

            // per 16-key block: exp2(f16x2) -> P fragment, l via ones-MMA, MMA2
            #pragma unroll
            for (int s2 = 0; s2 < 8; s2++) {
                __half2 s01 = __floats2half2_rn(sacc[2 * s2][0],     sacc[2 * s2][1]);
                __half2 s23 = __floats2half2_rn(sacc[2 * s2][2],     sacc[2 * s2][3]);
                __half2 s45 = __floats2half2_rn(sacc[2 * s2 + 1][0], sacc[2 * s2 + 1][1]);
                __half2 s67 = __floats2half2_rn(sacc[2 * s2 + 1][2], sacc[2 * s2 + 1][3]);
                uint32_t pf[4];
                EX2_H2(pf[0], *(uint32_t*)&s01);
                EX2_H2(pf[1], *(uint32_t*)&s23);
                EX2_H2(pf[2], *(uint32_t*)&s45);
                EX2_H2(pf[3], *(uint32_t*)&s67);

                mma16816(lacc[h], pf, ONES_H2, ONES_H2);

                #pragma unroll
                for (int jj = 0; jj < 4; jj++) {
                    int key = 16 * s2 + (lane & 15);
                    int ch  = 2 * jj + (lane >> 4);
                    uint32_t b0, b1, b2, b3;
                    LDSM_X4T(b0, b1, b2, b3, sbase + VB[cur] + SW8(key, ch));
                    mma16816(oacc[h][2 * jj],     pf, b0, b1);
                    mma16816(oacc[h][2 * jj + 1], pf, b2, b3);
                }
            }
        }
    }

    // ---- epilogue: fp32 partials for both halves ----
    #pragma unroll
    for (int h = 0; h < 2; h++) {
        float* Op = g_Op + (size_t)ks * TOT + ((size_t)b * SEQ + q0 + h * 128) * HS;
        #pragma unroll
        for (int jh = 0; jh < 8; jh++) {
            int col = 8 * jh + 2 * t;
            *(float2*)(Op + (size_t)prow0 * HS + col) =
                make_float2(oacc[h][jh][0], oacc[h][jh][1]);
            *(float2*)(Op + (size_t)prow1 * HS + col) =
                make_float2(oacc[h][jh][2], oacc[h][jh][3]);
        }
        if (t == 0) {
            size_t lb = (size_t)ks * BATCH * SEQ + (size_t)b * SEQ + q0 + h * 128;
            g_lp[lb + prow0] = lacc[h][0];
            g_lp[lb + prow1] = lacc[h][2];
        }
    }
}

// ---------------------------------------------------------------------------
// Combine split partials: out = (O0 + O1) / (l0 + l1). Round-11 exact.
// ---------------------------------------------------------------------------
__global__ __launch_bounds__(256)
void reduce_kernel(float* __restrict__ out)
{
    int gid = blockIdx.x * 256 + threadIdx.x;       // 0 .. TOT/4-1
    int row = gid >> 4;
    float4 a = *(const float4*)(g_Op + 4 * (size_t)gid);
    float4 c = *(const float4*)(g_Op + TOT + 4 * (size_t)gid);
    float inv = 1.0f / (g_lp[row] + g_lp[BATCH * SEQ + row]);
    float4 r;
    r.x = (a.x + c.x) * inv;
    r.y = (a.y + c.y) * inv;
    r.z = (a.z + c.z) * inv;
    r.w = (a.w + c.w) * inv;
    *(float4*)(out + 4 * (size_t)gid) = r;
}

// ---------------------------------------------------------------------------
extern "C" void kernel_launch(void* const* d_in, const int* in_sizes, int n_in,
                              void* d_out, int out_size)
{
    const float* x  = (const float*)d_in[0];
    const float* Wk = (const float*)d_in[1];
    const float* Wq = (const float*)d_in[2];
    const float* Wv = (const float*)d_in[3];
    float* out = (float*)d_out;

    (void)in_sizes; (void)n_in; (void)out_size;

    cudaFuncSetAttribute(attn_kernel,
                         cudaFuncAttributeMaxDynamicSharedMemorySize,
                         ATTN_SMEM_BYTES);
    cudaFuncSetAttribute(proj_kernel,
                         cudaFuncAttributeMaxDynamicSharedMemorySize,
                         PROJ_SMEM_BYTES);

    wconv_kernel<<<(24 * 32 * 24 + 255) / 256, 256>>>(Wk, Wq, Wv);
    proj_kernel<<<BATCH * SEQ / 64, 256, PROJ_SMEM_BYTES>>>(x);

    dim3 agrid(SEQ / 256, BATCH, KSPLIT);
    attn_kernel<<<agrid, 256, ATTN_SMEM_BYTES>>>();

    reduce_kernel<<<TOT / 4 / 256, 256>>>(out);
}

// round 17
// speedup vs baseline: 1.0757x; 1.0255x over previous
#include <cuda_runtime.h>
#include <cuda_fp16.h>
#include <cstdint>

#define EMB   768
#define HS    64
#define BATCH 4
#define SEQ   4096
#define KSPLIT 2
#define TOT   (BATCH * SEQ * HS)

// Projection outputs, fp16. Q pre-scaled by log2(e)/sqrt(768). Row-major.
__device__ __half g_Qh[TOT];
__device__ __half g_Kh[TOT];
__device__ __half g_Vh[TOT];
// Key-split partials: O fp32, l fp32.
__device__ float  g_Op[KSPLIT * TOT];
__device__ float  g_lp[KSPLIT * BATCH * SEQ];
// Pre-swizzled fp16 weight tile images: 24 K-blocks x (32 rows x 384B).
__device__ unsigned char g_Wimg[24 * 12288];

// ---------------------------------------------------------------------------
// helpers
// ---------------------------------------------------------------------------
__device__ __forceinline__ uint32_t smem_u32(const void* p) {
    uint32_t a;
    asm("{ .reg .u64 t; cvta.to.shared.u64 t, %1; cvt.u32.u64 %0, t; }"
        : "=r"(a) : "l"(p));
    return a;
}

#define LDSM_X4(r0, r1, r2, r3, addr) \
    asm volatile("ldmatrix.sync.aligned.m8n8.x4.shared.b16 {%0,%1,%2,%3}, [%4];" \
                 : "=r"(r0), "=r"(r1), "=r"(r2), "=r"(r3) : "r"(addr))

#define LDSM_X4T(r0, r1, r2, r3, addr) \
    asm volatile("ldmatrix.sync.aligned.m8n8.x4.trans.shared.b16 {%0,%1,%2,%3}, [%4];" \
                 : "=r"(r0), "=r"(r1), "=r"(r2), "=r"(r3) : "r"(addr))

__device__ __forceinline__ void mma16816(float* c, const uint32_t* a,
                                         uint32_t b0, uint32_t b1) {
    asm volatile(
        "mma.sync.aligned.m16n8k16.row.col.f32.f16.f16.f32 "
        "{%0,%1,%2,%3}, {%4,%5,%6,%7}, {%8,%9}, {%0,%1,%2,%3};"
        : "+f"(c[0]), "+f"(c[1]), "+f"(c[2]), "+f"(c[3])
        : "r"(a[0]), "r"(a[1]), "r"(a[2]), "r"(a[3]), "r"(b0), "r"(b1));
}

#define CP16(dst, src) \
    asm volatile("cp.async.cg.shared.global [%0], [%1], 16;" :: "r"(dst), "l"(src))
#define CP_COMMIT() asm volatile("cp.async.commit_group;")
#define CP_WAIT(n)  asm volatile("cp.async.wait_group %0;" :: "n"(n))

// fp16x2 exp2 (one MUFU op per two values)
#define EX2_H2(out, in) \
    asm("ex2.approx.f16x2 %0, %1;" : "=r"(out) : "r"(in))

// XOR-swizzled smem byte offset, 128B rows (8 x 16B chunks)
#define SW8(r, c)  ((uint32_t)((r) * 128 + ((((c) ^ ((r) & 7))) << 4)))
// W image swizzle: 384B rows = 24 chunks, XOR within each 8-chunk group
#define SWW(r, c)  ((uint32_t)((r) * 384 + ((((c) & ~7) | (((c) & 7) ^ ((r) & 7))) << 4)))

// Q scale = log2(e) / sqrt(768)
#define QSCALE 0.05205877870f
// all-ones fp16x2 B fragment
#define ONES_H2 0x3C003C00u

// ---------------------------------------------------------------------------
// One-time weight conversion (round-11 form).
// ---------------------------------------------------------------------------
__global__ __launch_bounds__(256)
void wconv_kernel(const float* __restrict__ Wk,
                  const float* __restrict__ Wq,
                  const float* __restrict__ Wv)
{
    int idx = blockIdx.x * 256 + threadIdx.x;
    if (idx >= 24 * 32 * 24) return;
    int c  = idx % 24;
    int r  = (idx / 24) % 32;
    int bi = idx / (24 * 32);
    int k  = bi * 32 + r;
    int n  = c * 8;
    const float* src = (n < 64 ? Wq : (n < 128 ? Wk : Wv)) + (size_t)k * HS + (n & 63);
    float4 f0 = *(const float4*)(src);
    float4 f1 = *(const float4*)(src + 4);
    __half2 h0 = __floats2half2_rn(f0.x, f0.y);
    __half2 h1 = __floats2half2_rn(f0.z, f0.w);
    __half2 h2 = __floats2half2_rn(f1.x, f1.y);
    __half2 h3 = __floats2half2_rn(f1.z, f1.w);
    uint4 u;
    u.x = *(uint32_t*)&h0; u.y = *(uint32_t*)&h1;
    u.z = *(uint32_t*)&h2; u.w = *(uint32_t*)&h3;
    *(uint4*)(g_Wimg + (size_t)bi * 12288 + SWW(r, c)) = u;
}

// ---------------------------------------------------------------------------
// Fused projection GEMM, fp16 mma, cp.async double-buffered (round-11 exact).
// ---------------------------------------------------------------------------
#define XF0 0u
#define XF1 8192u
#define WB0 16384u
#define WB1 28672u
#define XHO 40960u
#define PROJ_SMEM_BYTES 49152

__global__ __launch_bounds__(256, 2)
void proj_kernel(const float* __restrict__ x)
{
    extern __shared__ __align__(1024) char smem[];
    const uint32_t sb = smem_u32(smem);
    const uint32_t XF[2] = {sb + XF0, sb + XF1};
    const uint32_t WB[2] = {sb + WB0, sb + WB1};
    const uint32_t XH    = sb + XHO;

    const int tid  = threadIdx.x;
    const int lane = tid & 31;
    const int warp = tid >> 5;
    const int g    = lane >> 2;
    const int t    = lane & 3;
    const int wm   = warp & 3;
    const int wn   = warp >> 2;
    const int row0 = blockIdx.x * 64;

    #pragma unroll
    for (int i = 0; i < 2; i++) {
        int ch = tid + i * 256;
        int r = ch >> 3, c = ch & 7;
        CP16(XF[0] + (uint32_t)(r * 128 + c * 16),
             x + (size_t)(row0 + r) * EMB + c * 4);
    }
    #pragma unroll
    for (int i = 0; i < 3; i++) {
        int ch = tid + i * 256;
        CP16(WB[0] + (uint32_t)(ch * 16), g_Wimg + (size_t)(ch * 16));
    }
    CP_COMMIT();

    float cacc[12][4];
    #pragma unroll
    for (int j = 0; j < 12; j++)
        #pragma unroll
        for (int k = 0; k < 4; k++) cacc[j][k] = 0.f;

    for (int it = 0; it < EMB / 32; it++) {
        const int cur = it & 1;
        if (it + 1 < EMB / 32) {
            const int nxt = (it + 1) & 1;
            const int k0n = (it + 1) * 32;
            #pragma unroll
            for (int i = 0; i < 2; i++) {
                int ch = tid + i * 256;
                int r = ch >> 3, c = ch & 7;
                CP16(XF[nxt] + (uint32_t)(r * 128 + c * 16),
                     x + (size_t)(row0 + r) * EMB + k0n + c * 4);
            }
            #pragma unroll
            for (int i = 0; i < 3; i++) {
                int ch = tid + i * 256;
                CP16(WB[nxt] + (uint32_t)(ch * 16),
                     g_Wimg + (size_t)(it + 1) * 12288 + ch * 16);
            }
            CP_COMMIT();
            CP_WAIT(1);
        } else {
            CP_WAIT(0);
        }
        __syncthreads();

        {
            int r = tid >> 2, q = tid & 3;
            float4 f0 = *(const float4*)(smem + (XF[cur] - sb) + r * 128 + q * 32);
            float4 f1 = *(const float4*)(smem + (XF[cur] - sb) + r * 128 + q * 32 + 16);
            __half2 h0 = __floats2half2_rn(f0.x, f0.y);
            __half2 h1 = __floats2half2_rn(f0.z, f0.w);
            __half2 h2 = __floats2half2_rn(f1.x, f1.y);
            __half2 h3 = __floats2half2_rn(f1.z, f1.w);
            uint4 u;
            u.x = *(uint32_t*)&h0; u.y = *(uint32_t*)&h1;
            u.z = *(uint32_t*)&h2; u.w = *(uint32_t*)&h3;
            *(uint4*)(smem + XHO + SW8(r, q)) = u;
        }
        __syncthreads();

        uint32_t af[2][4];
        #pragma unroll
        for (int s = 0; s < 2; s++) {
            int row = wm * 16 + (lane & 15);
            int ch  = 2 * s + (lane >> 4);
            LDSM_X4(af[s][0], af[s][1], af[s][2], af[s][3], XH + SW8(row, ch));
        }
        #pragma unroll
        for (int s = 0; s < 2; s++) {
            #pragma unroll
            for (int jj = 0; jj < 6; jj++) {
                int row = 16 * s + (lane & 15);
                int ch  = 2 * (wn * 6 + jj) + (lane >> 4);
                uint32_t b0, b1, b2, b3;
                LDSM_X4T(b0, b1, b2, b3, WB[cur] + SWW(row, ch));
                mma16816(cacc[2 * jj],     af[s], b0, b1);
                mma16816(cacc[2 * jj + 1], af[s], b2, b3);
            }
        }
        __syncthreads();
    }

    const int prow0 = row0 + wm * 16 + g;
    const int prow1 = prow0 + 8;
    #pragma unroll
    for (int j = 0; j < 12; j++) {
        int col = wn * 96 + 8 * j + 2 * t;
        __half* dst;
        float mul;
        int lc;
        if (col < 64)       { dst = g_Qh; mul = QSCALE; lc = col; }
        else if (col < 128) { dst = g_Kh; mul = 1.0f;   lc = col - 64; }
        else                { dst = g_Vh; mul = 1.0f;   lc = col - 128; }
        __half2 v0 = __floats2half2_rn(cacc[j][0] * mul, cacc[j][1] * mul);
        __half2 v1 = __floats2half2_rn(cacc[j][2] * mul, cacc[j][3] * mul);
        *(__half2*)(dst + (size_t)prow0 * HS + lc) = v0;
        *(__half2*)(dst + (size_t)prow1 * HS + lc) = v1;
    }
}

// ---------------------------------------------------------------------------
// fp16 flash attention, BQ=256, single wave (128 CTAs), key-block-major inner
// loop: each K/V fragment is LDSM'd ONCE and feeds both query halves.
// SMEM: Q @0 (32K), K0 @32768, V0 @49152, K1 @65536, V1 @81920. Total 96K.
// ---------------------------------------------------------------------------
#define QOFS 0u
#define ATTN_SMEM_BYTES 98304
#define NIT (SEQ / 128 / KSPLIT)

__global__ __launch_bounds__(256)
void attn_kernel()
{
    extern __shared__ __align__(1024) char smem[];
    const uint32_t sbase = smem_u32(smem);

    const int tid  = threadIdx.x;
    const int lane = tid & 31;
    const int warp = tid >> 5;
    const int g    = lane >> 2;
    const int t    = lane & 3;
    const int wb   = warp * 16;
    const int b    = blockIdx.y;
    const int ks   = blockIdx.z;
    const int q0   = blockIdx.x * 256;

    const uint32_t KB[2] = {32768u, 65536u};
    const uint32_t VB[2] = {49152u, 81920u};

    const __half* Qg = g_Qh + ((size_t)b * SEQ + q0) * HS;
    const __half* Kg = g_Kh + ((size_t)b * SEQ + (size_t)ks * (SEQ / KSPLIT)) * HS;
    const __half* Vg = g_Vh + ((size_t)b * SEQ + (size_t)ks * (SEQ / KSPLIT)) * HS;

    // ---- prologue: Q (256x64) + K/V tile 0 ----
    #pragma unroll
    for (int i = 0; i < 8; i++) {
        int gc = tid + i * 256;
        int r = gc >> 3, c = gc & 7;
        CP16(sbase + QOFS + SW8(r, c), Qg + (size_t)r * HS + c * 8);
    }
    #pragma unroll
    for (int i = 0; i < 4; i++) {
        int gc = tid + i * 256;
        int r = gc >> 3, c = gc & 7;
        CP16(sbase + KB[0] + SW8(r, c), Kg + (size_t)r * HS + c * 8);
        CP16(sbase + VB[0] + SW8(r, c), Vg + (size_t)r * HS + c * 8);
    }
    CP_COMMIT();

    uint32_t qf[2][4][4];
    float lacc0[4], lacc1[4];
    float oacc0[8][4], oacc1[8][4];
    #pragma unroll
    for (int k = 0; k < 4; k++) { lacc0[k] = 0.f; lacc1[k] = 0.f; }
    #pragma unroll
    for (int j = 0; j < 8; j++)
        #pragma unroll
        for (int k = 0; k < 4; k++) { oacc0[j][k] = 0.f; oacc1[j][k] = 0.f; }

    const int prow0 = wb + g;
    const int prow1 = wb + g + 8;

    for (int it = 0; it < NIT; it++) {
        const int cur = it & 1;
        __syncthreads();

        if (it + 1 < NIT) {
            const int nxt = (it + 1) & 1;
            const int k0n = (it + 1) * 128;
            #pragma unroll
            for (int i = 0; i < 4; i++) {
                int gc = tid + i * 256;
                int r = gc >> 3, c = gc & 7;
                CP16(sbase + KB[nxt] + SW8(r, c),
                     Kg + (size_t)(k0n + r) * HS + c * 8);
                CP16(sbase + VB[nxt] + SW8(r, c),
                     Vg + (size_t)(k0n + r) * HS + c * 8);
            }
            CP_COMMIT();
            CP_WAIT(1);
        } else {
            CP_WAIT(0);
        }
        __syncthreads();

        if (it == 0) {
            #pragma unroll
            for (int h = 0; h < 2; h++)
                #pragma unroll
                for (int s = 0; s < 4; s++) {
                    int row = h * 128 + wb + (lane & 15);
                    int ch  = 2 * s + (lane >> 4);
                    LDSM_X4(qf[h][s][0], qf[h][s][1], qf[h][s][2], qf[h][s][3],
                            sbase + QOFS + SW8(row, ch));
                }
        }

        // ---- key-block-major: share K and V fragments across both halves ----
        #pragma unroll
        for (int jj = 0; jj < 8; jj++) {
            // S for this 16-key block, both halves
            float s0[2][4], s1[2][4];
            #pragma unroll
            for (int k = 0; k < 4; k++) {
                s0[0][k] = 0.f; s0[1][k] = 0.f;
                s1[0][k] = 0.f; s1[1][k] = 0.f;
            }
            #pragma unroll
            for (int s = 0; s < 4; s++) {
                int row = 8 * (2 * jj + (lane >> 4)) + (lane & 7);
                int ch  = 2 * s + ((lane >> 3) & 1);
                uint32_t b0, b1, b2, b3;
                LDSM_X4(b0, b1, b2, b3, sbase + KB[cur] + SW8(row, ch));
                mma16816(s0[0], qf[0][s], b0, b1);
                mma16816(s0[1], qf[0][s], b2, b3);
                mma16816(s1[0], qf[1][s], b0, b1);
                mma16816(s1[1], qf[1][s], b2, b3);
            }

            // exp2 -> P fragments for both halves; l via ones-MMA
            uint32_t pf0[4], pf1[4];
            {
                __half2 a01 = __floats2half2_rn(s0[0][0], s0[0][1]);
                __half2 a23 = __floats2half2_rn(s0[0][2], s0[0][3]);
                __half2 a45 = __floats2half2_rn(s0[1][0], s0[1][1]);
                __half2 a67 = __floats2half2_rn(s0[1][2], s0[1][3]);
                EX2_H2(pf0[0], *(uint32_t*)&a01);
                EX2_H2(pf0[1], *(uint32_t*)&a23);
                EX2_H2(pf0[2], *(uint32_t*)&a45);
                EX2_H2(pf0[3], *(uint32_t*)&a67);
                __half2 c01 = __floats2half2_rn(s1[0][0], s1[0][1]);
                __half2 c23 = __floats2half2_rn(s1[0][2], s1[0][3]);
                __half2 c45 = __floats2half2_rn(s1[1][0], s1[1][1]);
                __half2 c67 = __floats2half2_rn(s1[1][2], s1[1][3]);
                EX2_H2(pf1[0], *(uint32_t*)&c01);
                EX2_H2(pf1[1], *(uint32_t*)&c23);
                EX2_H2(pf1[2], *(uint32_t*)&c45);
                EX2_H2(pf1[3], *(uint32_t*)&c67);
            }
            mma16816(lacc0, pf0, ONES_H2, ONES_H2);
            mma16816(lacc1, pf1, ONES_H2, ONES_H2);

            // MMA2 for this key block: V fragments loaded once
            #pragma unroll
            for (int jv = 0; jv < 4; jv++) {
                int key = 16 * jj + (lane & 15);
                int ch  = 2 * jv + (lane >> 4);
                uint32_t b0, b1, b2, b3;
                LDSM_X4T(b0, b1, b2, b3, sbase + VB[cur] + SW8(key, ch));
                mma16816(oacc0[2 * jv],     pf0, b0, b1);
                mma16816(oacc0[2 * jv + 1], pf0, b2, b3);
                mma16816(oacc1[2 * jv],     pf1, b0, b1);
                mma16816(oacc1[2 * jv + 1], pf1, b2, b3);
            }
        }
    }

    // ---- epilogue: fp32 partials for both halves ----
    {
        float* Op = g_Op + (size_t)ks * TOT + ((size_t)b * SEQ + q0) * HS;
        #pragma unroll
        for (int jh = 0; jh < 8; jh++) {
            int col = 8 * jh + 2 * t;
            *(float2*)(Op + (size_t)prow0 * HS + col) =
                make_float2(oacc0[jh][0], oacc0[jh][1]);
            *(float2*)(Op + (size_t)prow1 * HS + col) =
                make_float2(oacc0[jh][2], oacc0[jh][3]);
        }
        float* Op1 = Op + (size_t)128 * HS;
        #pragma unroll
        for (int jh = 0; jh < 8; jh++) {
            int col = 8 * jh + 2 * t;
            *(float2*)(Op1 + (size_t)prow0 * HS + col) =
                make_float2(oacc1[jh][0], oacc1[jh][1]);
            *(float2*)(Op1 + (size_t)prow1 * HS + col) =
                make_float2(oacc1[jh][2], oacc1[jh][3]);
        }
        if (t == 0) {
            size_t lb = (size_t)ks * BATCH * SEQ + (size_t)b * SEQ + q0;
            g_lp[lb + prow0] = lacc0[0];
            g_lp[lb + prow1] = lacc0[2];
            g_lp[lb + 128 + prow0] = lacc1[0];
            g_lp[lb + 128 + prow1] = lacc1[2];
        }
    }
}

// ---------------------------------------------------------------------------
// Combine split partials: out = (O0 + O1) / (l0 + l1). Round-11 exact.
// ---------------------------------------------------------------------------
__global__ __launch_bounds__(256)
void reduce_kernel(float* __restrict__ out)
{
    int gid = blockIdx.x * 256 + threadIdx.x;       // 0 .. TOT/4-1
    int row = gid >> 4;
    float4 a = *(const float4*)(g_Op + 4 * (size_t)gid);
    float4 c = *(const float4*)(g_Op + TOT + 4 * (size_t)gid);
    float inv = 1.0f / (g_lp[row] + g_lp[BATCH * SEQ + row]);
    float4 r;
    r.x = (a.x + c.x) * inv;
    r.y = (a.y + c.y) * inv;
    r.z = (a.z + c.z) * inv;
    r.w = (a.w + c.w) * inv;
    *(float4*)(out + 4 * (size_t)gid) = r;
}

// ---------------------------------------------------------------------------
extern "C" void kernel_launch(void* const* d_in, const int* in_sizes, int n_in,
                              void* d_out, int out_size)
{
    const float* x  = (const float*)d_in[0];
    const float* Wk = (const float*)d_in[1];
    const float* Wq = (const float*)d_in[2];
    const float* Wv = (const float*)d_in[3];
    float* out = (float*)d_out;

    (void)in_sizes; (void)n_in; (void)out_size;

    cudaFuncSetAttribute(attn_kernel,
                         cudaFuncAttributeMaxDynamicSharedMemorySize,
                         ATTN_SMEM_BYTES);
    cudaFuncSetAttribute(proj_kernel,
                         cudaFuncAttributeMaxDynamicSharedMemorySize,
                         PROJ_SMEM_BYTES);

    wconv_kernel<<<(24 * 32 * 24 + 255) / 256, 256>>>(Wk, Wq, Wv);
    proj_kernel<<<BATCH * SEQ / 64, 256, PROJ_SMEM_BYTES>>>(x);

    dim3 agrid(SEQ / 256, BATCH, KSPLIT);
    attn_kernel<<<agrid, 256, ATTN_SMEM_BYTES>>>();

    reduce_kernel<<<TOT / 4 / 256, 256>>>(out);
}